// round 14
// baseline (speedup 1.0000x reference)
#include <cuda_runtime.h>
#include <cuda_bf16.h>
#include <math.h>
#include <stdint.h>
#include <cstdint>

// ---------------------------------------------------------------------------
// Problem dims (fixed)
// ---------------------------------------------------------------------------
#define DIM_B 16
#define DIM_T 512
#define DIM_S 128
#define DIM_M 16
#define DIM_D 512
#define NROWS (DIM_B * DIM_T)        // 8192
#define ERR_ROWS (DIM_S * DIM_M)     // 2048

#define TAU_STEP 0.07f
#define TAU_ERR  0.07f
#define RHO_ERR  0.85f
#define K_MAX    5
#define LAM_SELF 1.0f
#define LAM_SUCC 0.8f
#define LAM_PRED 0.4f
#define LAM_TOPO 0.5f
#define LOG16    2.772588722239781f

#define ROWS_PB  4                   // rows per sparse block

// Output layout (floats), in reference tuple order
#define ALPHA_OFF 0
#define GAMMA_OFF (ALPHA_OFF + NROWS * DIM_S)
#define BETA_OFF  (GAMMA_OFF + NROWS * DIM_S * DIM_M)
#define STEP_OFF  (BETA_OFF  + NROWS * DIM_S * DIM_M)
#define ERRO_OFF  (STEP_OFF  + NROWS * DIM_D)
#define AUX_OFF   (ERRO_OFF  + NROWS * DIM_D)
#define CMASK_OFF (AUX_OFF   + NROWS * 8)
#define RAW_OFF   (CMASK_OFF + NROWS * DIM_S)

// ---------------------------------------------------------------------------
// Scratch (static device globals: allocation-free)
// ---------------------------------------------------------------------------
__device__ float g_qstep[NROWS * DIM_D];
__device__ float g_qerr [NROWS * DIM_D];
__device__ float g_stepproto [DIM_S * DIM_D];
__device__ float g_stepprotoT[DIM_D * DIM_S];
__device__ float g_errproto[ERR_ROWS * DIM_D];

// ---------------------------------------------------------------------------
// TF32 helpers
// ---------------------------------------------------------------------------
__device__ __forceinline__ void split_tf32(float x, uint32_t& hi, uint32_t& lo) {
    uint32_t h = __float_as_uint(x) & 0xFFFFE000u;
    hi = h;
    lo = __float_as_uint(x - __uint_as_float(h));
}

__device__ __forceinline__ void mma_m16n8k8(float* c, const uint32_t* a, const uint32_t* b) {
    asm volatile(
        "mma.sync.aligned.m16n8k8.row.col.f32.tf32.tf32.f32 "
        "{%0,%1,%2,%3}, {%4,%5,%6,%7}, {%8,%9}, {%0,%1,%2,%3};\n"
        : "+f"(c[0]), "+f"(c[1]), "+f"(c[2]), "+f"(c[3])
        : "r"(a[0]), "r"(a[1]), "r"(a[2]), "r"(a[3]), "r"(b[0]), "r"(b[1]));
}

// ---------------------------------------------------------------------------
// TF32 (3x split) GEMM NT (R9 champion): C = scale*(A@B^T + bias)
// ---------------------------------------------------------------------------
template<int BM, int BN, int WM, int WN>
__global__ void __launch_bounds__((BM / WM) * (BN / WN) * 32)
mma_nt(const float* __restrict__ A, const float* __restrict__ B,
       const float* __restrict__ bias, float* __restrict__ C,
       int M, int N, int K, float scale)
{
    constexpr int WARPS_M = BM / WM;
    constexpr int WARPS_N = BN / WN;
    constexpr int NTHREADS = WARPS_M * WARPS_N * 32;
    constexpr int FM = WM / 16;
    constexpr int FN = WN / 8;
    constexpr int LDA = 20;
    constexpr int LA = BM * 4 / NTHREADS;
    constexpr int LB = BN * 4 / NTHREADS;

    __shared__ __align__(16) float sA[2][BM * LDA];
    __shared__ __align__(16) float sB[2][BN * LDA];

    const int tid = threadIdx.x;
    const int lane = tid & 31;
    const int warp = tid >> 5;
    const int gid = lane >> 2, tig = lane & 3;
    const int wm0 = (warp % WARPS_M) * WM;
    const int wn0 = (warp / WARPS_M) * WN;
    const int bm = blockIdx.y * BM;
    const int bn = blockIdx.x * BN;

    float acc[FM][FN][4];
#pragma unroll
    for (int i = 0; i < FM; i++)
#pragma unroll
        for (int j = 0; j < FN; j++)
#pragma unroll
            for (int q = 0; q < 4; q++) acc[i][j][q] = 0.f;

    float4 stageA[LA], stageB[LB];

    auto gload = [&](int kt) {
        int k0 = kt * 16;
#pragma unroll
        for (int i = 0; i < LA; i++) {
            int c = tid + i * NTHREADS;
            int row = c >> 2, kc = (c & 3) << 2;
            stageA[i] = *(const float4*)(A + (size_t)(bm + row) * K + k0 + kc);
        }
#pragma unroll
        for (int i = 0; i < LB; i++) {
            int c = tid + i * NTHREADS;
            int row = c >> 2, kc = (c & 3) << 2;
            stageB[i] = *(const float4*)(B + (size_t)(bn + row) * K + k0 + kc);
        }
    };

    auto sstore = [&](int buf) {
#pragma unroll
        for (int i = 0; i < LA; i++) {
            int c = tid + i * NTHREADS;
            int row = c >> 2, kc = (c & 3) << 2;
            *(float4*)(&sA[buf][row * LDA + kc]) = stageA[i];
        }
#pragma unroll
        for (int i = 0; i < LB; i++) {
            int c = tid + i * NTHREADS;
            int row = c >> 2, kc = (c & 3) << 2;
            *(float4*)(&sB[buf][row * LDA + kc]) = stageB[i];
        }
    };

    const int KT = K >> 4;
    gload(0);
    sstore(0);
    __syncthreads();

    int buf = 0;
    for (int kt = 0; kt < KT; kt++) {
        if (kt + 1 < KT) gload(kt + 1);

#pragma unroll
        for (int ks = 0; ks < 2; ks++) {
            uint32_t ahi[FM][4], alo[FM][4];
#pragma unroll
            for (int fm = 0; fm < FM; fm++) {
                int r = wm0 + fm * 16 + gid;
                float x0 = sA[buf][r * LDA + ks * 8 + tig];
                float x1 = sA[buf][(r + 8) * LDA + ks * 8 + tig];
                float x2 = sA[buf][r * LDA + ks * 8 + tig + 4];
                float x3 = sA[buf][(r + 8) * LDA + ks * 8 + tig + 4];
                split_tf32(x0, ahi[fm][0], alo[fm][0]);
                split_tf32(x1, ahi[fm][1], alo[fm][1]);
                split_tf32(x2, ahi[fm][2], alo[fm][2]);
                split_tf32(x3, ahi[fm][3], alo[fm][3]);
            }
#pragma unroll
            for (int fn = 0; fn < FN; fn++) {
                int n = wn0 + fn * 8 + gid;
                float y0 = sB[buf][n * LDA + ks * 8 + tig];
                float y1 = sB[buf][n * LDA + ks * 8 + tig + 4];
                uint32_t bhi[2], blo[2];
                split_tf32(y0, bhi[0], blo[0]);
                split_tf32(y1, bhi[1], blo[1]);
#pragma unroll
                for (int fm = 0; fm < FM; fm++) {
                    mma_m16n8k8(acc[fm][fn], alo[fm], bhi);
                    mma_m16n8k8(acc[fm][fn], ahi[fm], blo);
                    mma_m16n8k8(acc[fm][fn], ahi[fm], bhi);
                }
            }
        }

        if (kt + 1 < KT) sstore(buf ^ 1);
        __syncthreads();
        buf ^= 1;
    }

#pragma unroll
    for (int fm = 0; fm < FM; fm++) {
#pragma unroll
        for (int fn = 0; fn < FN; fn++) {
            int r0 = bm + wm0 + fm * 16 + gid;
            int c0 = bn + wn0 + fn * 8 + 2 * tig;
            float bx = 0.f, by = 0.f;
            if (bias) { bx = bias[c0]; by = bias[c0 + 1]; }
            float2 v0, v1;
            v0.x = (acc[fm][fn][0] + bx) * scale;
            v0.y = (acc[fm][fn][1] + by) * scale;
            v1.x = (acc[fm][fn][2] + bx) * scale;
            v1.y = (acc[fm][fn][3] + by) * scale;
            *(float2*)(C + (size_t)r0 * N + c0) = v0;
            *(float2*)(C + (size_t)(r0 + 8) * N + c0) = v1;
        }
    }
}

// ---------------------------------------------------------------------------
// Row-wise L2 normalize, width 512. One warp per row.
// ---------------------------------------------------------------------------
__global__ void normalize_rows(float* __restrict__ X, int R)
{
    int row = blockIdx.x * 4 + (threadIdx.x >> 5);
    int lane = threadIdx.x & 31;
    if (row >= R) return;
    float4* p = (float4*)(X + (size_t)row * DIM_D);
    float4 v[4];
    float ss = 0.f;
#pragma unroll
    for (int i = 0; i < 4; i++) {
        v[i] = p[lane + 32 * i];
        ss += v[i].x * v[i].x + v[i].y * v[i].y + v[i].z * v[i].z + v[i].w * v[i].w;
    }
#pragma unroll
    for (int o = 16; o > 0; o >>= 1) ss += __shfl_xor_sync(0xffffffffu, ss, o);
    float inv = 1.f / fmaxf(sqrtf(ss), 1e-8f);
#pragma unroll
    for (int i = 0; i < 4; i++) {
        v[i].x *= inv; v[i].y *= inv; v[i].z *= inv; v[i].w *= inv;
        p[lane + 32 * i] = v[i];
    }
}

// ---------------------------------------------------------------------------
// Transpose step_proto (128 x 512) -> (512 x 128)
// ---------------------------------------------------------------------------
__global__ void transpose_proto(const float* __restrict__ in, float* __restrict__ out)
{
    int idx = blockIdx.x * 256 + threadIdx.x;
    int s = idx >> 9, d = idx & 511;
    out[d * DIM_S + s] = in[idx];
}

// ---------------------------------------------------------------------------
// Warp-synchronous DAG scan (R9). One WARP per batch b; no barriers.
// ---------------------------------------------------------------------------
__global__ __launch_bounds__(32) void scan_kernel(
    const float* __restrict__ raw,
    float* __restrict__ alpha_out,
    float* __restrict__ aux)
{
    const unsigned FULL = 0xffffffffu;
    int b = blockIdx.x;
    int l = threadIdx.x;

    int s0 = 4 * l;
    bool h1[4], h2[4], h4[4], h8[4];
    float invc[4];
#pragma unroll
    for (int i = 0; i < 4; i++) {
        int s = s0 + i;
        h1[i] = s >= 1; h2[i] = s >= 2; h4[i] = s >= 4; h8[i] = s >= 8;
        int c = (int)h1[i] + (int)h2[i] + (int)h4[i] + (int)h8[i];
        invc[i] = c ? 1.f / (float)c : 0.f;
    }

    float p[4] = {1.f / DIM_S, 1.f / DIM_S, 1.f / DIM_S, 1.f / DIM_S};

    const float* rp = raw + (size_t)b * DIM_T * DIM_S;
    float* ap = alpha_out + (size_t)b * DIM_T * DIM_S;
    float4 rv = *(const float4*)(rp + s0);

    for (int t = 0; t < DIM_T; t++) {
        float4 cur = rv;
        if (t + 1 < DIM_T) rv = *(const float4*)(rp + (size_t)(t + 1) * DIM_S + s0);
        float craw[4] = {cur.x, cur.y, cur.z, cur.w};

        float u1[4], u2[4];
#pragma unroll
        for (int i = 0; i < 4; i++) {
            u1[i] = __shfl_up_sync(FULL, p[i], 1);
            u2[i] = __shfl_up_sync(FULL, p[i], 2);
        }
        float v1[4] = {u1[3], p[0], p[1], p[2]};
        float v2[4] = {u1[2], u1[3], p[0], p[1]};

        float e[4];
        float les = 0.f, lms = 0.f, lmm = -1e30f;
#pragma unroll
        for (int i = 0; i < 4; i++) {
            float pm = 0.f, px = -1e30f;
            if (h1[i]) { pm += v1[i]; px = fmaxf(px, v1[i]); }
            if (h2[i]) { pm += v2[i]; px = fmaxf(px, v2[i]); }
            if (h4[i]) { pm += u1[i]; px = fmaxf(px, u1[i]); }
            if (h8[i]) { pm += u2[i]; px = fmaxf(px, u2[i]); }
            float pmean = pm * invc[i];
            float pmax  = h1[i] ? px : 0.f;
            float mass = fmaxf(LAM_SELF * p[i] + LAM_SUCC * pmax + LAM_PRED * pmean, 1e-8f);
            float logit = craw[i] + LAM_TOPO * __logf(mass);
            e[i] = __expf(logit);
            les += e[i];
            lms += mass;
            lmm = fmaxf(lmm, mass);
        }

#pragma unroll
        for (int o = 16; o > 0; o >>= 1) {
            les += __shfl_xor_sync(FULL, les, o);
            lms += __shfl_xor_sync(FULL, lms, o);
            lmm = fmaxf(lmm, __shfl_xor_sync(FULL, lmm, o));
        }

        float invZ = __fdividef(1.f, les);
        float4 av;
        av.x = e[0] * invZ; av.y = e[1] * invZ;
        av.z = e[2] * invZ; av.w = e[3] * invZ;
        *(float4*)(ap + (size_t)t * DIM_S + s0) = av;
        p[0] = av.x; p[1] = av.y; p[2] = av.z; p[3] = av.w;

        if (l == 0) {
            float* ax = aux + ((size_t)b * DIM_T + t) * 8;
            ax[5] = lms * (1.0f / DIM_S);
            ax[6] = lmm;
        }
    }
}

// ---------------------------------------------------------------------------
// Sparse kernel, 4 ROWS PER BLOCK. Consecutive t rows select overlapping
// steps; err_proto tiles are read once per UNION step for all 4 rows,
// cutting L2 read traffic ~2.5-4x. Union built via ballot (deterministic).
// ---------------------------------------------------------------------------
__global__ __launch_bounds__(128) void sparse_kernel(
    const float* __restrict__ alpha,    // [NROWS, S]
    const float* __restrict__ qerr,     // [NROWS, D]
    const float* __restrict__ errproto, // [S*M, D]
    float* __restrict__ out)
{
    const unsigned FULL = 0xffffffffu;
    int row0 = blockIdx.x * ROWS_PB;
    int tid = threadIdx.x;
    int lane = tid & 31, w = tid >> 5;

    __shared__ __align__(16) float sh_q[ROWS_PB][DIM_D];       // 8 KB
    __shared__ float warp_vals[ROWS_PB][4][K_MAX];
    __shared__ int   warp_idx [ROWS_PB][4][K_MAX];
    __shared__ int   sel_idx  [ROWS_PB][K_MAX];
    __shared__ float sel_alpha[ROWS_PB][K_MAX];
    __shared__ int   sel_flag [ROWS_PB][DIM_S];                // 2 KB
    __shared__ int   sh_count [ROWS_PB];
    __shared__ float sh_top1[ROWS_PB], sh_top2[ROWS_PB];
    __shared__ float sh_ulog [ROWS_PB * K_MAX][DIM_M][ROWS_PB]; // 5 KB
    __shared__ float sh_beta [ROWS_PB][K_MAX][DIM_M];
    __shared__ float sh_gamma[ROWS_PB][K_MAX][DIM_M];
    __shared__ float sh_H    [ROWS_PB][K_MAX];
    __shared__ float sh_gsum [ROWS_PB][K_MAX];
    __shared__ int   ulist[ROWS_PB * K_MAX], umask[ROWS_PB * K_MAX];
    __shared__ int   uslot[DIM_S];
    __shared__ int   wcnt[4];
    __shared__ float redA[ROWS_PB][4], redB[ROWS_PB][4];

    // ---- load alpha (regs) and q rows (smem) ----
    float a[ROWS_PB];
#pragma unroll
    for (int r = 0; r < ROWS_PB; r++) {
        a[r] = alpha[(size_t)(row0 + r) * DIM_S + tid];
        sel_flag[r][tid] = 0;
        ((float4*)sh_q[r])[tid] = ((const float4*)(qerr + (size_t)(row0 + r) * DIM_D))[tid];
    }
    __syncthreads();

    // ---- per-warp top-5 per row ----
#pragma unroll
    for (int r = 0; r < ROWS_PB; r++) {
        float v = a[r];
        int id = tid;
#pragma unroll
        for (int j = 0; j < K_MAX; j++) {
            float bv = v; int bi = id;
#pragma unroll
            for (int o = 16; o > 0; o >>= 1) {
                float ov = __shfl_xor_sync(FULL, bv, o);
                int   oi = __shfl_xor_sync(FULL, bi, o);
                if (ov > bv || (ov == bv && oi < bi)) { bv = ov; bi = oi; }
            }
            if (lane == 0) { warp_vals[r][w][j] = bv; warp_idx[r][w][j] = bi; }
            if (id == bi) v = -1e30f;
        }
    }
    __syncthreads();

    // ---- threads 0..3 merge their row's 20 candidates in parallel ----
    if (tid < ROWS_PB) {
        int r = tid;
        float vals[20]; int ids[20]; bool used[20];
#pragma unroll
        for (int w2 = 0; w2 < 4; w2++)
#pragma unroll
            for (int j = 0; j < K_MAX; j++) {
                vals[w2 * K_MAX + j] = warp_vals[r][w2][j];
                ids [w2 * K_MAX + j] = warp_idx [r][w2][j];
                used[w2 * K_MAX + j] = false;
            }
        float prefix = 0.f, top1 = 0.f, top2 = 0.f;
        int cnt = 0;
        for (int j = 0; j < K_MAX; j++) {
            int best = -1;
            for (int c = 0; c < 20; c++) {
                if (used[c]) continue;
                if (best < 0 || vals[c] > vals[best] ||
                    (vals[c] == vals[best] && ids[c] < ids[best])) best = c;
            }
            used[best] = true;
            if (j == 0) top1 = vals[best];
            if (j == 1) top2 = vals[best];
            bool keep = prefix < RHO_ERR;
            prefix += vals[best];
            if (keep) {
                sel_idx[r][cnt] = ids[best];
                sel_alpha[r][cnt] = vals[best];
                sel_flag[r][ids[best]] = cnt + 1;
                cnt++;
            }
        }
        sh_count[r] = cnt;
        sh_top1[r] = top1;
        sh_top2[r] = top2;
    }
    __syncthreads();

    // ---- union of selected steps (ballot prefix: deterministic order) ----
    int mask = 0;
#pragma unroll
    for (int r = 0; r < ROWS_PB; r++)
        if (sel_flag[r][tid]) mask |= (1 << r);
    unsigned bal = __ballot_sync(FULL, mask != 0);
    if (lane == 0) wcnt[w] = __popc(bal);
    __syncthreads();
    int base = 0;
    for (int w2 = 0; w2 < w; w2++) base += wcnt[w2];
    int ucnt = wcnt[0] + wcnt[1] + wcnt[2] + wcnt[3];
    if (mask != 0) {
        int pos = base + __popc(bal & ((1u << lane) - 1u));
        ulist[pos] = tid;
        umask[pos] = mask;
        uslot[tid] = pos;
    }
    __syncthreads();

    // ---- logits over union steps: warp w handles m = 4w..4w+3 ----
    for (int k = 0; k < ucnt; k++) {
        int s = ulist[k], msk = umask[k];
        const float* ep = errproto + (size_t)(s * DIM_M + w * 4) * DIM_D;
#pragma unroll
        for (int mi = 0; mi < 4; mi++) {
            const float4* er = (const float4*)(ep + (size_t)mi * DIM_D);
            float4 e0 = er[lane], e1 = er[32 + lane], e2 = er[64 + lane], e3 = er[96 + lane];
#pragma unroll
            for (int r = 0; r < ROWS_PB; r++) {
                if (!((msk >> r) & 1)) continue;
                const float4* qr = (const float4*)sh_q[r];
                float4 q0 = qr[lane], q1 = qr[32 + lane], q2 = qr[64 + lane], q3 = qr[96 + lane];
                float sum = q0.x*e0.x + q0.y*e0.y + q0.z*e0.z + q0.w*e0.w
                          + q1.x*e1.x + q1.y*e1.y + q1.z*e1.z + q1.w*e1.w
                          + q2.x*e2.x + q2.y*e2.y + q2.z*e2.z + q2.w*e2.w
                          + q3.x*e3.x + q3.y*e3.y + q3.z*e3.z + q3.w*e3.w;
#pragma unroll
                for (int o = 16; o > 0; o >>= 1) sum += __shfl_xor_sync(FULL, sum, o);
                if (lane == 0) sh_ulog[k][w * 4 + mi][r] = sum * (1.0f / TAU_ERR);
            }
        }
    }
    __syncthreads();

    // ---- softmax per (row, selected step): threads 0..19 ----
    if (tid < ROWS_PB * K_MAX) {
        int r = tid / K_MAX, j = tid % K_MAX;
        if (j < sh_count[r]) {
            int s = sel_idx[r][j];
            int k = uslot[s];
            float l[DIM_M];
            float mx = -1e30f;
#pragma unroll
            for (int m = 0; m < DIM_M; m++) { l[m] = sh_ulog[k][m][r]; mx = fmaxf(mx, l[m]); }
            float sum = 0.f;
#pragma unroll
            for (int m = 0; m < DIM_M; m++) { l[m] = __expf(l[m] - mx); sum += l[m]; }
            float inv = 1.f / sum;
            float as_ = sel_alpha[r][j];
            float H = 0.f, gs = 0.f;
#pragma unroll
            for (int m = 0; m < DIM_M; m++) {
                float be = l[m] * inv;
                sh_beta[r][j][m] = be;
                float g = as_ * be;
                sh_gamma[r][j][m] = g;
                gs += g;
                H -= be * __logf(fmaxf(be, 1e-8f));
            }
            sh_H[r][j] = H;
            sh_gsum[r][j] = gs;
        }
    }
    __syncthreads();

    // ---- err_sem over union steps: tile read ONCE for all 4 rows ----
    {
        float4 acc[ROWS_PB];
#pragma unroll
        for (int r = 0; r < ROWS_PB; r++) acc[r] = make_float4(0.f, 0.f, 0.f, 0.f);

        for (int k = 0; k < ucnt; k++) {
            int s = ulist[k], msk = umask[k];
            int jr[ROWS_PB];
#pragma unroll
            for (int r = 0; r < ROWS_PB; r++)
                jr[r] = ((msk >> r) & 1) ? (sel_flag[r][s] - 1) : -1;
            const float* bptr = errproto + (size_t)s * DIM_M * DIM_D + tid * 4;
#pragma unroll
            for (int m = 0; m < DIM_M; m++) {
                float4 e = *(const float4*)(bptr + (size_t)m * DIM_D);
#pragma unroll
                for (int r = 0; r < ROWS_PB; r++) {
                    if (jr[r] >= 0) {
                        float g = sh_gamma[r][jr[r]][m];
                        acc[r].x += g * e.x; acc[r].y += g * e.y;
                        acc[r].z += g * e.z; acc[r].w += g * e.w;
                    }
                }
            }
        }
#pragma unroll
        for (int r = 0; r < ROWS_PB; r++)
            *(float4*)(out + ERRO_OFF + (size_t)(row0 + r) * DIM_D + tid * 4) = acc[r];
    }

    // ---- coalesced beta/gamma writes + cmask per row ----
#pragma unroll
    for (int r = 0; r < ROWS_PB; r++) {
        float4* brow = (float4*)(out + BETA_OFF  + (size_t)(row0 + r) * (DIM_S * DIM_M));
        float4* grow = (float4*)(out + GAMMA_OFF + (size_t)(row0 + r) * (DIM_S * DIM_M));
#pragma unroll
        for (int q = 0; q < 4; q++) {
            int fi = q * 128 + tid;
            int s  = fi >> 2;
            int m0 = (fi & 3) << 2;
            int fj = sel_flag[r][s];
            float4 bv, gv;
            if (fj) {
                int j = fj - 1;
                bv = make_float4(sh_beta[r][j][m0], sh_beta[r][j][m0+1],
                                 sh_beta[r][j][m0+2], sh_beta[r][j][m0+3]);
                gv = make_float4(sh_gamma[r][j][m0], sh_gamma[r][j][m0+1],
                                 sh_gamma[r][j][m0+2], sh_gamma[r][j][m0+3]);
            } else {
                bv = make_float4(0.0625f, 0.0625f, 0.0625f, 0.0625f);
                gv = make_float4(0.f, 0.f, 0.f, 0.f);
            }
            brow[fi] = bv;
            grow[fi] = gv;
        }
        out[CMASK_OFF + (size_t)(row0 + r) * DIM_S + tid] = sel_flag[r][tid] ? 1.f : 0.f;
    }

    // ---- aux reductions per row ----
#pragma unroll
    for (int r = 0; r < ROWS_PB; r++) {
        int f = sel_flag[r][tid];
        float ent = -a[r] * __logf(fmaxf(a[r], 1e-8f));
        float ht = (f ? sh_H[r][f - 1] : LOG16) * a[r];
#pragma unroll
        for (int o = 16; o > 0; o >>= 1) {
            ent += __shfl_xor_sync(FULL, ent, o);
            ht  += __shfl_xor_sync(FULL, ht, o);
        }
        if (lane == 0) { redA[r][w] = ent; redB[r][w] = ht; }
    }
    __syncthreads();
    if (tid < ROWS_PB) {
        int r = tid;
        float entropy = redA[r][0] + redA[r][1] + redA[r][2] + redA[r][3];
        float hsum    = redB[r][0] + redB[r][1] + redB[r][2] + redB[r][3];
        float gsum = 0.f;
        int cnt = sh_count[r];
        for (int j = 0; j < cnt; j++) gsum += sh_gsum[r][j];
        float* ax = out + AUX_OFF + (size_t)(row0 + r) * 8;
        ax[0] = entropy;
        ax[1] = sh_top1[r];
        ax[2] = sh_top1[r] - sh_top2[r];
        ax[3] = gsum;
        ax[4] = hsum;
        ax[7] = (float)cnt / (float)K_MAX;
    }
}

// ---------------------------------------------------------------------------
// Launch (qstep GEMM in the profiled slot)
// ---------------------------------------------------------------------------
extern "C" void kernel_launch(void* const* d_in, const int* in_sizes, int n_in,
                              void* d_out, int out_size)
{
    (void)in_sizes; (void)n_in; (void)out_size;
    const float* frame   = (const float*)d_in[0];
    const float* stepp   = (const float*)d_in[1];
    const float* errp    = (const float*)d_in[2];
    const float* Wq_step = (const float*)d_in[3];
    const float* bq_step = (const float*)d_in[4];
    const float* Wq_err  = (const float*)d_in[5];
    const float* bq_err  = (const float*)d_in[6];
    const float* Wa_step = (const float*)d_in[7];
    const float* ba_step = (const float*)d_in[8];
    const float* Wa_err  = (const float*)d_in[9];
    const float* ba_err  = (const float*)d_in[10];
    float* out = (float*)d_out;

    float *qstep, *qerr, *sproto, *sprotoT, *eproto;
    cudaGetSymbolAddress((void**)&qstep,   g_qstep);
    cudaGetSymbolAddress((void**)&qerr,    g_qerr);
    cudaGetSymbolAddress((void**)&sproto,  g_stepproto);
    cudaGetSymbolAddress((void**)&sprotoT, g_stepprotoT);
    cudaGetSymbolAddress((void**)&eproto,  g_errproto);

    // 0: step-proto projection
    mma_nt<64, 128, 32, 64><<<dim3(DIM_D / 128, DIM_S / 64), 128>>>(
        stepp, Wa_step, ba_step, sproto, DIM_S, DIM_D, DIM_D, 1.f);
    // 1
    normalize_rows<<<DIM_S / 4, 128>>>(sproto, DIM_S);
    // 2
    transpose_proto<<<(DIM_S * DIM_D) / 256, 256>>>(sproto, sprotoT);
    // 3: qstep projection  <-- profiled slot
    mma_nt<128, 128, 32, 64><<<dim3(DIM_D / 128, NROWS / 128), 256>>>(
        frame, Wq_step, bq_step, qstep, NROWS, DIM_D, DIM_D, 1.f);
    // 4
    normalize_rows<<<NROWS / 4, 128>>>(qstep, NROWS);
    // 5: err-proto projection
    mma_nt<128, 128, 32, 64><<<dim3(DIM_D / 128, ERR_ROWS / 128), 256>>>(
        errp, Wa_err, ba_err, eproto, ERR_ROWS, DIM_D, DIM_D, 1.f);
    // 6
    normalize_rows<<<ERR_ROWS / 4, 128>>>(eproto, ERR_ROWS);
    // 7: qerr projection
    mma_nt<128, 128, 32, 64><<<dim3(DIM_D / 128, NROWS / 128), 256>>>(
        frame, Wq_err, bq_err, qerr, NROWS, DIM_D, DIM_D, 1.f);
    // 8
    normalize_rows<<<NROWS / 4, 128>>>(qerr, NROWS);
    // 9: raw_step_logits = q_step @ step_proto^T / tau
    mma_nt<64, 128, 32, 64><<<dim3(DIM_S / 128, NROWS / 64), 128>>>(
        qstep, sproto, nullptr, out + RAW_OFF, NROWS, DIM_S, DIM_D, 1.f / TAU_STEP);
    // 10: warp-synchronous DAG scan
    scan_kernel<<<DIM_B, 32>>>(out + RAW_OFF, out + ALPHA_OFF, out + AUX_OFF);
    // 11: sparse error path (4 rows per block)
    sparse_kernel<<<NROWS / ROWS_PB, 128>>>(out + ALPHA_OFF, qerr, eproto, out);
    // 12: step_sem_obs = alpha @ step_proto
    mma_nt<128, 128, 32, 64><<<dim3(DIM_D / 128, NROWS / 128), 256>>>(
        out + ALPHA_OFF, sprotoT, nullptr, out + STEP_OFF, NROWS, DIM_D, DIM_S, 1.f);
}